// round 2
// baseline (speedup 1.0000x reference)
#include <cuda_runtime.h>
#include <cuda_bf16.h>
#include <cstdint>

// Problem constants
#define BB   4
#define SS   2048
#define HH   16
#define DH   64
#define DM   1024
#define BHT  (BB*HH)          // 64

// Scratch (device globals: allocation-free)
__device__ float g_qh [(size_t)BB*HH*SS*DH];   // [B,H,S,Dh]
__device__ float g_kh [(size_t)BB*HH*SS*DH];
__device__ float g_vh [(size_t)BB*HH*SS*DH];
__device__ float g_ctx[(size_t)BB*HH*SS*DH];
__device__ float g_rsum[(size_t)BB*HH*SS];     // softmax row sums

// FMA-only exp (avoids MUFU throughput wall: 268M exps x2 passes)
__device__ __forceinline__ float fexp(float x) {
    float y = x * 1.4426950408889634f;      // x * log2(e)
    float r = rintf(y);
    float c = (y - r) * 0.6931471805599453f; // back to natural frac, |c| <= 0.347
    float p = 1.3888889e-3f;
    p = fmaf(p, c, 8.3333333e-3f);
    p = fmaf(p, c, 4.1666667e-2f);
    p = fmaf(p, c, 1.6666667e-1f);
    p = fmaf(p, c, 0.5f);
    p = fmaf(p, c, 1.0f);
    p = fmaf(p, c, 1.0f);
    return p * __int_as_float(((int)r + 127) << 23);
}

// ---------------------------------------------------------------------------
// K0: zero row sums (graph replays must reset the atomic accumulators)
// ---------------------------------------------------------------------------
__global__ void k_zero_rsum() {
    int i = blockIdx.x * 256 + threadIdx.x;
    if (i < BB*HH*SS) g_rsum[i] = 0.0f;
}

// ---------------------------------------------------------------------------
// K1: fused QKV projection.  y = x @ W^T + b, scattered to [B,H,S,Dh].
// 128x128x16 fp32 tile, 256 threads, 8x8 per thread. blockIdx.z selects q/k/v.
// ---------------------------------------------------------------------------
__global__ __launch_bounds__(256) void k_qkv_proj(
    const float* __restrict__ xq, const float* __restrict__ xk, const float* __restrict__ xv,
    const float* __restrict__ wq, const float* __restrict__ wk, const float* __restrict__ wv,
    const float* __restrict__ bq, const float* __restrict__ bk, const float* __restrict__ bv)
{
    __shared__ float As[16][132];
    __shared__ float Bs[16][132];
    int z = blockIdx.z;
    const float* X  = (z == 0) ? xq : (z == 1) ? xk : xv;
    const float* W  = (z == 0) ? wq : (z == 1) ? wk : wv;
    const float* Bi = (z == 0) ? bq : (z == 1) ? bk : bv;
    float*       O  = (z == 0) ? g_qh : (z == 1) ? g_kh : g_vh;

    int tid = threadIdx.x;
    int tx = tid & 15, ty = tid >> 4;
    int m0 = blockIdx.y * 128, n0 = blockIdx.x * 128;

    float acc[8][8];
    #pragma unroll
    for (int i = 0; i < 8; i++)
        #pragma unroll
        for (int j = 0; j < 8; j++) acc[i][j] = 0.0f;

    for (int k0 = 0; k0 < DM; k0 += 16) {
        #pragma unroll
        for (int u = 0; u < 2; u++) {
            int id = tid + u * 256;
            int r = id >> 2, c = (id & 3) << 2;
            float4 a = *(const float4*)(X + (size_t)(m0 + r) * DM + k0 + c);
            As[c+0][r] = a.x; As[c+1][r] = a.y; As[c+2][r] = a.z; As[c+3][r] = a.w;
            float4 w4 = *(const float4*)(W + (size_t)(n0 + r) * DM + k0 + c);
            Bs[c+0][r] = w4.x; Bs[c+1][r] = w4.y; Bs[c+2][r] = w4.z; Bs[c+3][r] = w4.w;
        }
        __syncthreads();
        #pragma unroll
        for (int kk = 0; kk < 16; kk++) {
            float a[8], b[8];
            #pragma unroll
            for (int i = 0; i < 8; i++) a[i] = As[kk][ty * 8 + i];
            #pragma unroll
            for (int j = 0; j < 8; j++) b[j] = Bs[kk][tx * 8 + j];
            #pragma unroll
            for (int i = 0; i < 8; i++)
                #pragma unroll
                for (int j = 0; j < 8; j++) acc[i][j] = fmaf(a[i], b[j], acc[i][j]);
        }
        __syncthreads();
    }
    // epilogue: scatter to [B,H,S,Dh] with bias
    #pragma unroll
    for (int i = 0; i < 8; i++) {
        int m  = m0 + ty * 8 + i;
        int b_ = m >> 11, s_ = m & (SS - 1);
        #pragma unroll
        for (int j = 0; j < 8; j++) {
            int n  = n0 + tx * 8 + j;
            int h  = n >> 6, dh = n & 63;
            O[((size_t)(b_ * HH + h) * SS + s_) * DH + dh] = acc[i][j] + Bi[n];
        }
    }
}

// ---------------------------------------------------------------------------
// K2: raw attention logits s = (q . k)/8 + mask, written into the final score
// output region, plus per-row sum(exp(s)) accumulated via atomics.
// Per (b,h): GEMM M=S, N=S, K=64.  128x128 tile.
// ---------------------------------------------------------------------------
__global__ __launch_bounds__(256) void k_scores(
    const float* __restrict__ mask, float* __restrict__ score)
{
    __shared__ float As[16][132];
    __shared__ float Bs[16][132];
    int bh  = blockIdx.z;
    int tid = threadIdx.x;
    int tx = tid & 15, ty = tid >> 4;
    int q0 = blockIdx.y * 128, n0 = blockIdx.x * 128;
    const float* Q = g_qh + (size_t)bh * SS * DH;
    const float* K = g_kh + (size_t)bh * SS * DH;

    float acc[8][8];
    #pragma unroll
    for (int i = 0; i < 8; i++)
        #pragma unroll
        for (int j = 0; j < 8; j++) acc[i][j] = 0.0f;

    for (int k0 = 0; k0 < DH; k0 += 16) {
        #pragma unroll
        for (int u = 0; u < 2; u++) {
            int id = tid + u * 256;
            int r = id >> 2, c = (id & 3) << 2;
            float4 a = *(const float4*)(Q + (size_t)(q0 + r) * DH + k0 + c);
            As[c+0][r] = a.x; As[c+1][r] = a.y; As[c+2][r] = a.z; As[c+3][r] = a.w;
            float4 b = *(const float4*)(K + (size_t)(n0 + r) * DH + k0 + c);
            Bs[c+0][r] = b.x; Bs[c+1][r] = b.y; Bs[c+2][r] = b.z; Bs[c+3][r] = b.w;
        }
        __syncthreads();
        #pragma unroll
        for (int kk = 0; kk < 16; kk++) {
            float a[8], b[8];
            #pragma unroll
            for (int i = 0; i < 8; i++) a[i] = As[kk][ty * 8 + i];
            #pragma unroll
            for (int j = 0; j < 8; j++) b[j] = Bs[kk][tx * 8 + j];
            #pragma unroll
            for (int i = 0; i < 8; i++)
                #pragma unroll
                for (int j = 0; j < 8; j++) acc[i][j] = fmaf(a[i], b[j], acc[i][j]);
        }
        __syncthreads();
    }

    float psum[8];
    #pragma unroll
    for (int i = 0; i < 8; i++) psum[i] = 0.0f;
    size_t sbase = (size_t)bh * SS * SS;
    #pragma unroll
    for (int i = 0; i < 8; i++) {
        int q = q0 + ty * 8 + i;
        #pragma unroll
        for (int j = 0; j < 8; j++) {
            int n = n0 + tx * 8 + j;
            float s = fmaf(acc[i][j], 0.125f, mask[(size_t)q * SS + n]);
            score[sbase + (size_t)q * SS + n] = s;
            psum[i] += fexp(s);
        }
    }
    __syncthreads();
    float* red = &As[0][0];                 // 128*16 <= 16*132
    #pragma unroll
    for (int i = 0; i < 8; i++) red[(ty * 8 + i) * 16 + tx] = psum[i];
    __syncthreads();
    if (tid < 128) {
        float s = 0.0f;
        #pragma unroll
        for (int t = 0; t < 16; t++) s += red[tid * 16 + t];
        atomicAdd(&g_rsum[(size_t)bh * SS + q0 + tid], s);
    }
}

// ---------------------------------------------------------------------------
// K3: normalize scores in place (p = exp(s)/l) and compute ctx = P @ V.
// Per (b,h, 128-row q tile): GEMM M=128, N=64, K=S with BK=16.
// ---------------------------------------------------------------------------
__global__ __launch_bounds__(256) void k_pv(float* __restrict__ score)
{
    __shared__ float As[16][132];   // p^T chunk
    __shared__ float Vs[16][68];    // v chunk [k][dh]
    __shared__ float invs[128];
    int bh  = blockIdx.y;
    int q0  = blockIdx.x * 128;
    int tid = threadIdx.x;
    int tx = tid & 15, ty = tid >> 4;

    if (tid < 128) invs[tid] = 1.0f / g_rsum[(size_t)bh * SS + q0 + tid];
    __syncthreads();

    const float* V = g_vh + (size_t)bh * SS * DH;
    float* Sc = score + (size_t)bh * SS * SS + (size_t)q0 * SS;

    float acc[8][4];
    #pragma unroll
    for (int i = 0; i < 8; i++)
        #pragma unroll
        for (int j = 0; j < 4; j++) acc[i][j] = 0.0f;

    for (int k0 = 0; k0 < SS; k0 += 16) {
        #pragma unroll
        for (int u = 0; u < 2; u++) {
            int id = tid + u * 256;
            int r = id >> 2, c = (id & 3) << 2;
            float4 sv = *(const float4*)(Sc + (size_t)r * SS + k0 + c);
            float iv = invs[r];
            float4 p;
            p.x = fexp(sv.x) * iv;  p.y = fexp(sv.y) * iv;
            p.z = fexp(sv.z) * iv;  p.w = fexp(sv.w) * iv;
            *(float4*)(Sc + (size_t)r * SS + k0 + c) = p;   // final normalized score
            As[c+0][r] = p.x; As[c+1][r] = p.y; As[c+2][r] = p.z; As[c+3][r] = p.w;
        }
        {
            int r = tid >> 4, c = (tid & 15) << 2;
            float4 vv = *(const float4*)(V + (size_t)(k0 + r) * DH + c);
            *(float4*)&Vs[r][c] = vv;
        }
        __syncthreads();
        #pragma unroll
        for (int kk = 0; kk < 16; kk++) {
            float a[8], b[4];
            #pragma unroll
            for (int i = 0; i < 8; i++) a[i] = As[kk][ty * 8 + i];
            #pragma unroll
            for (int j = 0; j < 4; j++) b[j] = Vs[kk][tx * 4 + j];
            #pragma unroll
            for (int i = 0; i < 8; i++)
                #pragma unroll
                for (int j = 0; j < 4; j++) acc[i][j] = fmaf(a[i], b[j], acc[i][j]);
        }
        __syncthreads();
    }
    float* C = g_ctx + (size_t)bh * SS * DH + (size_t)q0 * DH;
    #pragma unroll
    for (int i = 0; i < 8; i++)
        #pragma unroll
        for (int j = 0; j < 4; j++)
            C[(size_t)(ty * 8 + i) * DH + tx * 4 + j] = acc[i][j];
}

// ---------------------------------------------------------------------------
// K4: output projection.  x = ctx(gathered to [B*S, DM]) @ Wo^T + bo
// ---------------------------------------------------------------------------
__global__ __launch_bounds__(256) void k_oproj(
    const float* __restrict__ wo, const float* __restrict__ bo, float* __restrict__ out)
{
    __shared__ float As[16][132];
    __shared__ float Bs[16][132];
    int tid = threadIdx.x;
    int tx = tid & 15, ty = tid >> 4;
    int m0 = blockIdx.y * 128, n0 = blockIdx.x * 128;

    float acc[8][8];
    #pragma unroll
    for (int i = 0; i < 8; i++)
        #pragma unroll
        for (int j = 0; j < 8; j++) acc[i][j] = 0.0f;

    for (int k0 = 0; k0 < DM; k0 += 16) {
        #pragma unroll
        for (int u = 0; u < 2; u++) {
            int id = tid + u * 256;
            int r = id >> 2, c = (id & 3) << 2;
            int m = m0 + r;
            int b_ = m >> 11, s_ = m & (SS - 1);
            int kidx = k0 + c;
            int h = kidx >> 6, dh = kidx & 63;   // float4 never crosses a head boundary
            float4 a = *(const float4*)(g_ctx + ((size_t)(b_ * HH + h) * SS + s_) * DH + dh);
            As[c+0][r] = a.x; As[c+1][r] = a.y; As[c+2][r] = a.z; As[c+3][r] = a.w;
            float4 w4 = *(const float4*)(wo + (size_t)(n0 + r) * DM + k0 + c);
            Bs[c+0][r] = w4.x; Bs[c+1][r] = w4.y; Bs[c+2][r] = w4.z; Bs[c+3][r] = w4.w;
        }
        __syncthreads();
        #pragma unroll
        for (int kk = 0; kk < 16; kk++) {
            float a[8], b[8];
            #pragma unroll
            for (int i = 0; i < 8; i++) a[i] = As[kk][ty * 8 + i];
            #pragma unroll
            for (int j = 0; j < 8; j++) b[j] = Bs[kk][tx * 8 + j];
            #pragma unroll
            for (int i = 0; i < 8; i++)
                #pragma unroll
                for (int j = 0; j < 8; j++) acc[i][j] = fmaf(a[i], b[j], acc[i][j]);
        }
        __syncthreads();
    }
    #pragma unroll
    for (int i = 0; i < 8; i++) {
        int m = m0 + ty * 8 + i;
        #pragma unroll
        for (int j = 0; j < 8; j++) {
            int n = n0 + tx * 8 + j;
            out[(size_t)m * DM + n] = acc[i][j] + bo[n];
        }
    }
}

// ---------------------------------------------------------------------------
extern "C" void kernel_launch(void* const* d_in, const int* in_sizes, int n_in,
                              void* d_out, int out_size)
{
    const float* q    = (const float*)d_in[0];
    const float* k    = (const float*)d_in[1];
    const float* v    = (const float*)d_in[2];
    const float* mask = (const float*)d_in[3];
    const float* w_q  = (const float*)d_in[4];
    const float* b_q  = (const float*)d_in[5];
    const float* w_k  = (const float*)d_in[6];
    const float* b_k  = (const float*)d_in[7];
    const float* w_v  = (const float*)d_in[8];
    const float* b_v  = (const float*)d_in[9];
    const float* w_o  = (const float*)d_in[10];
    const float* b_o  = (const float*)d_in[11];

    float* out   = (float*)d_out;                        // x: [B,S,DM]
    float* score = out + (size_t)BB * SS * DM;           // score: [B,H,S,S]

    k_zero_rsum<<<(BB*HH*SS + 255) / 256, 256>>>();
    k_qkv_proj<<<dim3(DM/128, (BB*SS)/128, 3), 256>>>(q, k, v, w_q, w_k, w_v, b_q, b_k, b_v);
    k_scores<<<dim3(SS/128, SS/128, BHT), 256>>>(mask, score);
    k_pv<<<dim3(SS/128, BHT), 256>>>(score);
    k_oproj<<<dim3(DM/128, (BB*SS)/128), 256>>>(w_o, b_o, out);
}

// round 3
// speedup vs baseline: 2.1151x; 2.1151x over previous
#include <cuda_runtime.h>
#include <cuda_bf16.h>
#include <cstdint>

// Problem constants
#define BB   4
#define SS   2048
#define HH   16
#define DH   64
#define DM   1024
#define BHT  (BB*HH)          // 64

// Scratch (device globals: allocation-free)
__device__ float g_qh [(size_t)BB*HH*SS*DH];   // [B,H,S,Dh]
__device__ float g_kh [(size_t)BB*HH*SS*DH];
__device__ float g_vh [(size_t)BB*HH*SS*DH];
__device__ float g_ctx[(size_t)BB*HH*SS*DH];
__device__ float g_rsum[(size_t)BB*HH*SS];     // softmax row sums

// fp32 -> tf32 with round-to-nearest (keeps operand error ~2.4e-4)
__device__ __forceinline__ uint32_t tf32c(float x) {
    uint32_t u;
    asm("cvt.rna.tf32.f32 %0, %1;" : "=r"(u) : "f"(x));
    return u;
}

// m16n8k8 tf32 MMA, fp32 accumulate
__device__ __forceinline__ void mma8(float c[4], const uint32_t a[4], const uint32_t b[2]) {
    asm volatile(
        "mma.sync.aligned.m16n8k8.row.col.f32.tf32.tf32.f32 "
        "{%0,%1,%2,%3},{%4,%5,%6,%7},{%8,%9},{%0,%1,%2,%3};"
        : "+f"(c[0]), "+f"(c[1]), "+f"(c[2]), "+f"(c[3])
        : "r"(a[0]), "r"(a[1]), "r"(a[2]), "r"(a[3]), "r"(b[0]), "r"(b[1]));
}

// FMA-only exp (avoids MUFU throughput wall on 268M x2 exps)
__device__ __forceinline__ float fexp(float x) {
    float y = x * 1.4426950408889634f;
    float r = rintf(y);
    float c = (y - r) * 0.6931471805599453f;
    float p = 1.3888889e-3f;
    p = fmaf(p, c, 8.3333333e-3f);
    p = fmaf(p, c, 4.1666667e-2f);
    p = fmaf(p, c, 1.6666667e-1f);
    p = fmaf(p, c, 0.5f);
    p = fmaf(p, c, 1.0f);
    p = fmaf(p, c, 1.0f);
    return p * __int_as_float(((int)r + 127) << 23);
}

// ---------------------------------------------------------------------------
__global__ void k_zero_rsum() {
    int i = blockIdx.x * 256 + threadIdx.x;
    if (i < BB*HH*SS) g_rsum[i] = 0.0f;
}

// ---------------------------------------------------------------------------
// K1: fused QKV projection, tf32 tensor cores.
// 128x128 block, BK=16, 256 threads = 8 warps (2x4), warp tile 64x32.
// ---------------------------------------------------------------------------
__global__ __launch_bounds__(256) void k_qkv_proj(
    const float* __restrict__ xq, const float* __restrict__ xk, const float* __restrict__ xv,
    const float* __restrict__ wq, const float* __restrict__ wk, const float* __restrict__ wv,
    const float* __restrict__ bq, const float* __restrict__ bk, const float* __restrict__ bv)
{
    __shared__ uint32_t As[128*20];   // [m][k], stride 20: conflict-free frag LDS
    __shared__ uint32_t Bs[128*20];   // [n][k]
    int z = blockIdx.z;
    const float* X  = (z == 0) ? xq : (z == 1) ? xk : xv;
    const float* W  = (z == 0) ? wq : (z == 1) ? wk : wv;
    const float* Bi = (z == 0) ? bq : (z == 1) ? bk : bv;
    float*       O  = (z == 0) ? g_qh : (z == 1) ? g_kh : g_vh;

    int tid = threadIdx.x;
    int lane = tid & 31, wid = tid >> 5;
    int g = lane >> 2, ct = lane & 3;
    int mb = (wid >> 2) * 64, nb = (wid & 3) * 32;
    int m0 = blockIdx.y * 128, n0 = blockIdx.x * 128;

    float c[4][4][4];
    #pragma unroll
    for (int i = 0; i < 4; i++)
        #pragma unroll
        for (int j = 0; j < 4; j++)
            #pragma unroll
            for (int t = 0; t < 4; t++) c[i][j][t] = 0.0f;

    for (int k0 = 0; k0 < DM; k0 += 16) {
        #pragma unroll
        for (int u = 0; u < 2; u++) {
            int id = tid + u * 256;
            int r = id >> 2, c4 = (id & 3) << 2;
            float4 a = *(const float4*)(X + (size_t)(m0 + r) * DM + k0 + c4);
            uint4 ta = make_uint4(tf32c(a.x), tf32c(a.y), tf32c(a.z), tf32c(a.w));
            *(uint4*)&As[r * 20 + c4] = ta;
            float4 w4 = *(const float4*)(W + (size_t)(n0 + r) * DM + k0 + c4);
            uint4 tb = make_uint4(tf32c(w4.x), tf32c(w4.y), tf32c(w4.z), tf32c(w4.w));
            *(uint4*)&Bs[r * 20 + c4] = tb;
        }
        __syncthreads();
        #pragma unroll
        for (int ks = 0; ks < 16; ks += 8) {
            uint32_t af[4][4], bf[4][2];
            #pragma unroll
            for (int i = 0; i < 4; i++) {
                int r0 = (mb + i * 16 + g) * 20 + ks + ct;
                af[i][0] = As[r0];       af[i][2] = As[r0 + 4];
                af[i][1] = As[r0 + 160]; af[i][3] = As[r0 + 164];
            }
            #pragma unroll
            for (int j = 0; j < 4; j++) {
                int b0 = (nb + j * 8 + g) * 20 + ks + ct;
                bf[j][0] = Bs[b0]; bf[j][1] = Bs[b0 + 4];
            }
            #pragma unroll
            for (int i = 0; i < 4; i++)
                #pragma unroll
                for (int j = 0; j < 4; j++) mma8(c[i][j], af[i], bf[j]);
        }
        __syncthreads();
    }
    // epilogue: bias + scatter to [B,H,S,Dh]
    #pragma unroll
    for (int i = 0; i < 4; i++) {
        int row = m0 + mb + i * 16 + g;
        int b_ = row >> 11, s_ = row & (SS - 1);
        #pragma unroll
        for (int j = 0; j < 4; j++) {
            int col = n0 + nb + j * 8 + ct * 2;
            int h = col >> 6, dh = col & 63;
            float2 bi = *(const float2*)&Bi[col];
            float2 v0 = make_float2(c[i][j][0] + bi.x, c[i][j][1] + bi.y);
            float2 v1 = make_float2(c[i][j][2] + bi.x, c[i][j][3] + bi.y);
            size_t base = ((size_t)(b_ * HH + h) * SS + s_) * DH + dh;
            *(float2*)&O[base] = v0;
            *(float2*)&O[base + 8 * DH] = v1;
        }
    }
}

// ---------------------------------------------------------------------------
// K2: raw logits s = (q.k)/8 + mask into score output region + rowsum(exp).
// tf32 mma, K=64. 128x128 block per (bh, qtile, ntile).
// ---------------------------------------------------------------------------
__global__ __launch_bounds__(256) void k_scores(
    const float* __restrict__ mask, float* __restrict__ score)
{
    __shared__ uint32_t As[128*20];
    __shared__ uint32_t Bs[128*20];
    __shared__ float rowacc[128];
    int bh  = blockIdx.z;
    int tid = threadIdx.x;
    int lane = tid & 31, wid = tid >> 5;
    int g = lane >> 2, ct = lane & 3;
    int mb = (wid >> 2) * 64, nb = (wid & 3) * 32;
    int q0 = blockIdx.y * 128, n0 = blockIdx.x * 128;
    const float* Q = g_qh + (size_t)bh * SS * DH;
    const float* K = g_kh + (size_t)bh * SS * DH;

    if (tid < 128) rowacc[tid] = 0.0f;

    float c[4][4][4];
    #pragma unroll
    for (int i = 0; i < 4; i++)
        #pragma unroll
        for (int j = 0; j < 4; j++)
            #pragma unroll
            for (int t = 0; t < 4; t++) c[i][j][t] = 0.0f;

    for (int k0 = 0; k0 < DH; k0 += 16) {
        #pragma unroll
        for (int u = 0; u < 2; u++) {
            int id = tid + u * 256;
            int r = id >> 2, c4 = (id & 3) << 2;
            float4 a = *(const float4*)(Q + (size_t)(q0 + r) * DH + k0 + c4);
            *(uint4*)&As[r * 20 + c4] = make_uint4(tf32c(a.x), tf32c(a.y), tf32c(a.z), tf32c(a.w));
            float4 b = *(const float4*)(K + (size_t)(n0 + r) * DH + k0 + c4);
            *(uint4*)&Bs[r * 20 + c4] = make_uint4(tf32c(b.x), tf32c(b.y), tf32c(b.z), tf32c(b.w));
        }
        __syncthreads();
        #pragma unroll
        for (int ks = 0; ks < 16; ks += 8) {
            uint32_t af[4][4], bf[4][2];
            #pragma unroll
            for (int i = 0; i < 4; i++) {
                int r0 = (mb + i * 16 + g) * 20 + ks + ct;
                af[i][0] = As[r0];       af[i][2] = As[r0 + 4];
                af[i][1] = As[r0 + 160]; af[i][3] = As[r0 + 164];
            }
            #pragma unroll
            for (int j = 0; j < 4; j++) {
                int b0 = (nb + j * 8 + g) * 20 + ks + ct;
                bf[j][0] = Bs[b0]; bf[j][1] = Bs[b0 + 4];
            }
            #pragma unroll
            for (int i = 0; i < 4; i++)
                #pragma unroll
                for (int j = 0; j < 4; j++) mma8(c[i][j], af[i], bf[j]);
        }
        __syncthreads();
    }

    size_t sbase = (size_t)bh * SS * SS;
    float rs[4][2];
    #pragma unroll
    for (int i = 0; i < 4; i++) { rs[i][0] = 0.0f; rs[i][1] = 0.0f; }

    #pragma unroll
    for (int i = 0; i < 4; i++) {
        int row = q0 + mb + i * 16 + g;
        #pragma unroll
        for (int j = 0; j < 4; j++) {
            int col = n0 + nb + j * 8 + ct * 2;
            float2 mk0 = *(const float2*)&mask[(size_t)row * SS + col];
            float s0 = fmaf(c[i][j][0], 0.125f, mk0.x);
            float s1 = fmaf(c[i][j][1], 0.125f, mk0.y);
            *(float2*)&score[sbase + (size_t)row * SS + col] = make_float2(s0, s1);
            rs[i][0] += fexp(s0) + fexp(s1);
            float2 mk1 = *(const float2*)&mask[(size_t)(row + 8) * SS + col];
            float s2 = fmaf(c[i][j][2], 0.125f, mk1.x);
            float s3 = fmaf(c[i][j][3], 0.125f, mk1.y);
            *(float2*)&score[sbase + (size_t)(row + 8) * SS + col] = make_float2(s2, s3);
            rs[i][1] += fexp(s2) + fexp(s3);
        }
    }
    __syncthreads();
    #pragma unroll
    for (int i = 0; i < 4; i++) {
        #pragma unroll
        for (int h = 0; h < 2; h++) {
            float v = rs[i][h];
            v += __shfl_xor_sync(0xffffffff, v, 1);
            v += __shfl_xor_sync(0xffffffff, v, 2);
            if (ct == 0) atomicAdd(&rowacc[mb + i * 16 + h * 8 + g], v);
        }
    }
    __syncthreads();
    if (tid < 128) atomicAdd(&g_rsum[(size_t)bh * SS + q0 + tid], rowacc[tid]);
}

// ---------------------------------------------------------------------------
// K3: normalize score in place (p = exp(s)/l) + ctx = P@V via tf32 mma.
// Block: 128 q-rows x 64 dh, K=2048. 8 warps (4x2), warp tile 32x32.
// ---------------------------------------------------------------------------
__global__ __launch_bounds__(256) void k_pv(float* __restrict__ score)
{
    __shared__ uint32_t As[128*20];   // p [m=128][k=16]
    __shared__ uint32_t Bs[64*20];    // v [n=64][k=16]
    __shared__ float invs[128];
    int bh  = blockIdx.y;
    int q0  = blockIdx.x * 128;
    int tid = threadIdx.x;
    int lane = tid & 31, wid = tid >> 5;
    int g = lane >> 2, ct = lane & 3;
    int mb = (wid >> 1) * 32, nb = (wid & 1) * 32;

    if (tid < 128) invs[tid] = 1.0f / g_rsum[(size_t)bh * SS + q0 + tid];
    __syncthreads();

    const float* V = g_vh + (size_t)bh * SS * DH;
    float* Sc = score + (size_t)bh * SS * SS + (size_t)q0 * SS;

    float c[2][4][4];
    #pragma unroll
    for (int i = 0; i < 2; i++)
        #pragma unroll
        for (int j = 0; j < 4; j++)
            #pragma unroll
            for (int t = 0; t < 4; t++) c[i][j][t] = 0.0f;

    for (int k0 = 0; k0 < SS; k0 += 16) {
        #pragma unroll
        for (int u = 0; u < 2; u++) {
            int id = tid + u * 256;
            int r = id >> 2, c4 = (id & 3) << 2;
            float4 sv = *(const float4*)(Sc + (size_t)r * SS + k0 + c4);
            float iv = invs[r];
            float4 p;
            p.x = fexp(sv.x) * iv;  p.y = fexp(sv.y) * iv;
            p.z = fexp(sv.z) * iv;  p.w = fexp(sv.w) * iv;
            *(float4*)(Sc + (size_t)r * SS + k0 + c4) = p;   // final normalized score
            *(uint4*)&As[r * 20 + c4] = make_uint4(tf32c(p.x), tf32c(p.y), tf32c(p.z), tf32c(p.w));
        }
        {
            int kv = tid & 15, dh4 = (tid >> 4) << 2;   // conflict-free transpose store
            float4 vv = *(const float4*)(V + (size_t)(k0 + kv) * DH + dh4);
            Bs[(dh4 + 0) * 20 + kv] = tf32c(vv.x);
            Bs[(dh4 + 1) * 20 + kv] = tf32c(vv.y);
            Bs[(dh4 + 2) * 20 + kv] = tf32c(vv.z);
            Bs[(dh4 + 3) * 20 + kv] = tf32c(vv.w);
        }
        __syncthreads();
        #pragma unroll
        for (int ks = 0; ks < 16; ks += 8) {
            uint32_t af[2][4], bf[4][2];
            #pragma unroll
            for (int i = 0; i < 2; i++) {
                int r0 = (mb + i * 16 + g) * 20 + ks + ct;
                af[i][0] = As[r0];       af[i][2] = As[r0 + 4];
                af[i][1] = As[r0 + 160]; af[i][3] = As[r0 + 164];
            }
            #pragma unroll
            for (int j = 0; j < 4; j++) {
                int b0 = (nb + j * 8 + g) * 20 + ks + ct;
                bf[j][0] = Bs[b0]; bf[j][1] = Bs[b0 + 4];
            }
            #pragma unroll
            for (int i = 0; i < 2; i++)
                #pragma unroll
                for (int j = 0; j < 4; j++) mma8(c[i][j], af[i], bf[j]);
        }
        __syncthreads();
    }
    float* C = g_ctx + (size_t)bh * SS * DH + (size_t)q0 * DH;
    #pragma unroll
    for (int i = 0; i < 2; i++) {
        int row = mb + i * 16 + g;
        #pragma unroll
        for (int j = 0; j < 4; j++) {
            int col = nb + j * 8 + ct * 2;
            *(float2*)&C[(size_t)row * DH + col]       = make_float2(c[i][j][0], c[i][j][1]);
            *(float2*)&C[(size_t)(row + 8) * DH + col] = make_float2(c[i][j][2], c[i][j][3]);
        }
    }
}

// ---------------------------------------------------------------------------
// K4: output projection via tf32 mma.  x = ctx(gather) @ Wo^T + bo
// ---------------------------------------------------------------------------
__global__ __launch_bounds__(256) void k_oproj(
    const float* __restrict__ wo, const float* __restrict__ bo, float* __restrict__ out)
{
    __shared__ uint32_t As[128*20];
    __shared__ uint32_t Bs[128*20];
    int tid = threadIdx.x;
    int lane = tid & 31, wid = tid >> 5;
    int g = lane >> 2, ct = lane & 3;
    int mb = (wid >> 2) * 64, nb = (wid & 3) * 32;
    int m0 = blockIdx.y * 128, n0 = blockIdx.x * 128;

    float c[4][4][4];
    #pragma unroll
    for (int i = 0; i < 4; i++)
        #pragma unroll
        for (int j = 0; j < 4; j++)
            #pragma unroll
            for (int t = 0; t < 4; t++) c[i][j][t] = 0.0f;

    for (int k0 = 0; k0 < DM; k0 += 16) {
        #pragma unroll
        for (int u = 0; u < 2; u++) {
            int id = tid + u * 256;
            int r = id >> 2, c4 = (id & 3) << 2;
            int m = m0 + r;
            int b_ = m >> 11, s_ = m & (SS - 1);
            int kidx = k0 + c4;
            int h = kidx >> 6, dh = kidx & 63;
            float4 a = *(const float4*)(g_ctx + ((size_t)(b_ * HH + h) * SS + s_) * DH + dh);
            *(uint4*)&As[r * 20 + c4] = make_uint4(tf32c(a.x), tf32c(a.y), tf32c(a.z), tf32c(a.w));
            float4 w4 = *(const float4*)(wo + (size_t)(n0 + r) * DM + k0 + c4);
            *(uint4*)&Bs[r * 20 + c4] = make_uint4(tf32c(w4.x), tf32c(w4.y), tf32c(w4.z), tf32c(w4.w));
        }
        __syncthreads();
        #pragma unroll
        for (int ks = 0; ks < 16; ks += 8) {
            uint32_t af[4][4], bf[4][2];
            #pragma unroll
            for (int i = 0; i < 4; i++) {
                int r0 = (mb + i * 16 + g) * 20 + ks + ct;
                af[i][0] = As[r0];       af[i][2] = As[r0 + 4];
                af[i][1] = As[r0 + 160]; af[i][3] = As[r0 + 164];
            }
            #pragma unroll
            for (int j = 0; j < 4; j++) {
                int b0 = (nb + j * 8 + g) * 20 + ks + ct;
                bf[j][0] = Bs[b0]; bf[j][1] = Bs[b0 + 4];
            }
            #pragma unroll
            for (int i = 0; i < 4; i++)
                #pragma unroll
                for (int j = 0; j < 4; j++) mma8(c[i][j], af[i], bf[j]);
        }
        __syncthreads();
    }
    #pragma unroll
    for (int i = 0; i < 4; i++) {
        int row = m0 + mb + i * 16 + g;
        #pragma unroll
        for (int j = 0; j < 4; j++) {
            int col = n0 + nb + j * 8 + ct * 2;
            float2 bi = *(const float2*)&bo[col];
            *(float2*)&out[(size_t)row * DM + col] =
                make_float2(c[i][j][0] + bi.x, c[i][j][1] + bi.y);
            *(float2*)&out[(size_t)(row + 8) * DM + col] =
                make_float2(c[i][j][2] + bi.x, c[i][j][3] + bi.y);
        }
    }
}

// ---------------------------------------------------------------------------
extern "C" void kernel_launch(void* const* d_in, const int* in_sizes, int n_in,
                              void* d_out, int out_size)
{
    const float* q    = (const float*)d_in[0];
    const float* k    = (const float*)d_in[1];
    const float* v    = (const float*)d_in[2];
    const float* mask = (const float*)d_in[3];
    const float* w_q  = (const float*)d_in[4];
    const float* b_q  = (const float*)d_in[5];
    const float* w_k  = (const float*)d_in[6];
    const float* b_k  = (const float*)d_in[7];
    const float* w_v  = (const float*)d_in[8];
    const float* b_v  = (const float*)d_in[9];
    const float* w_o  = (const float*)d_in[10];
    const float* b_o  = (const float*)d_in[11];

    float* out   = (float*)d_out;                        // x: [B,S,DM]
    float* score = out + (size_t)BB * SS * DM;           // score: [B,H,S,S]

    k_zero_rsum<<<(BB*HH*SS + 255) / 256, 256>>>();
    k_qkv_proj<<<dim3(DM/128, (BB*SS)/128, 3), 256>>>(q, k, v, w_q, w_k, w_v, b_q, b_k, b_v);
    k_scores<<<dim3(SS/128, SS/128, BHT), 256>>>(mask, score);
    k_pv<<<dim3(SS/128, BHT), 256>>>(score);
    k_oproj<<<dim3(DM/128, (BB*SS)/128), 256>>>(w_o, b_o, out);
}

// round 4
// speedup vs baseline: 2.1611x; 1.0218x over previous
#include <cuda_runtime.h>
#include <cuda_bf16.h>
#include <cstdint>

// Problem constants
#define BB   4
#define SS   2048
#define HH   16
#define DH   64
#define DM   1024
#define BHT  (BB*HH)          // 64

// Scratch (device globals: allocation-free)
__device__ float g_qh [(size_t)BB*HH*SS*DH];   // [B,H,S,Dh]
__device__ float g_kh [(size_t)BB*HH*SS*DH];
__device__ float g_vh [(size_t)BB*HH*SS*DH];
__device__ float g_ctx[(size_t)BB*HH*SS*DH];

// fp32 -> tf32 round-to-nearest
__device__ __forceinline__ uint32_t tf32c(float x) {
    uint32_t u;
    asm("cvt.rna.tf32.f32 %0, %1;" : "=r"(u) : "f"(x));
    return u;
}

// m16n8k8 tf32 MMA, fp32 accumulate
__device__ __forceinline__ void mma8(float c[4], const uint32_t a[4], const uint32_t b[2]) {
    asm volatile(
        "mma.sync.aligned.m16n8k8.row.col.f32.tf32.tf32.f32 "
        "{%0,%1,%2,%3},{%4,%5,%6,%7},{%8,%9},{%0,%1,%2,%3};"
        : "+f"(c[0]), "+f"(c[1]), "+f"(c[2]), "+f"(c[3])
        : "r"(a[0]), "r"(a[1]), "r"(a[2]), "r"(a[3]), "r"(b[0]), "r"(b[1]));
}

// FMA-only exp (MUFU throughput wall avoidance)
__device__ __forceinline__ float fexp(float x) {
    float y = x * 1.4426950408889634f;
    float r = rintf(y);
    float c = (y - r) * 0.6931471805599453f;
    float p = 1.3888889e-3f;
    p = fmaf(p, c, 8.3333333e-3f);
    p = fmaf(p, c, 4.1666667e-2f);
    p = fmaf(p, c, 1.6666667e-1f);
    p = fmaf(p, c, 0.5f);
    p = fmaf(p, c, 1.0f);
    p = fmaf(p, c, 1.0f);
    return p * __int_as_float(((int)r + 127) << 23);
}

// ---------------------------------------------------------------------------
// K1: fused QKV projection, tf32 tensor cores. (unchanged from round 2)
// ---------------------------------------------------------------------------
__global__ __launch_bounds__(256) void k_qkv_proj(
    const float* __restrict__ xq, const float* __restrict__ xk, const float* __restrict__ xv,
    const float* __restrict__ wq, const float* __restrict__ wk, const float* __restrict__ wv,
    const float* __restrict__ bq, const float* __restrict__ bk, const float* __restrict__ bv)
{
    __shared__ uint32_t As[128*20];
    __shared__ uint32_t Bs[128*20];
    int z = blockIdx.z;
    const float* X  = (z == 0) ? xq : (z == 1) ? xk : xv;
    const float* W  = (z == 0) ? wq : (z == 1) ? wk : wv;
    const float* Bi = (z == 0) ? bq : (z == 1) ? bk : bv;
    float*       O  = (z == 0) ? g_qh : (z == 1) ? g_kh : g_vh;

    int tid = threadIdx.x;
    int lane = tid & 31, wid = tid >> 5;
    int g = lane >> 2, ct = lane & 3;
    int mb = (wid >> 2) * 64, nb = (wid & 3) * 32;
    int m0 = blockIdx.y * 128, n0 = blockIdx.x * 128;

    float c[4][4][4];
    #pragma unroll
    for (int i = 0; i < 4; i++)
        #pragma unroll
        for (int j = 0; j < 4; j++)
            #pragma unroll
            for (int t = 0; t < 4; t++) c[i][j][t] = 0.0f;

    for (int k0 = 0; k0 < DM; k0 += 16) {
        #pragma unroll
        for (int u = 0; u < 2; u++) {
            int id = tid + u * 256;
            int r = id >> 2, c4 = (id & 3) << 2;
            float4 a = *(const float4*)(X + (size_t)(m0 + r) * DM + k0 + c4);
            *(uint4*)&As[r * 20 + c4] = make_uint4(tf32c(a.x), tf32c(a.y), tf32c(a.z), tf32c(a.w));
            float4 w4 = *(const float4*)(W + (size_t)(n0 + r) * DM + k0 + c4);
            *(uint4*)&Bs[r * 20 + c4] = make_uint4(tf32c(w4.x), tf32c(w4.y), tf32c(w4.z), tf32c(w4.w));
        }
        __syncthreads();
        #pragma unroll
        for (int ks = 0; ks < 16; ks += 8) {
            uint32_t af[4][4], bf[4][2];
            #pragma unroll
            for (int i = 0; i < 4; i++) {
                int r0 = (mb + i * 16 + g) * 20 + ks + ct;
                af[i][0] = As[r0];       af[i][2] = As[r0 + 4];
                af[i][1] = As[r0 + 160]; af[i][3] = As[r0 + 164];
            }
            #pragma unroll
            for (int j = 0; j < 4; j++) {
                int b0 = (nb + j * 8 + g) * 20 + ks + ct;
                bf[j][0] = Bs[b0]; bf[j][1] = Bs[b0 + 4];
            }
            #pragma unroll
            for (int i = 0; i < 4; i++)
                #pragma unroll
                for (int j = 0; j < 4; j++) mma8(c[i][j], af[i], bf[j]);
        }
        __syncthreads();
    }
    #pragma unroll
    for (int i = 0; i < 4; i++) {
        int row = m0 + mb + i * 16 + g;
        int b_ = row >> 11, s_ = row & (SS - 1);
        #pragma unroll
        for (int j = 0; j < 4; j++) {
            int col = n0 + nb + j * 8 + ct * 2;
            int h = col >> 6, dh = col & 63;
            float2 bi = *(const float2*)&Bi[col];
            float2 v0 = make_float2(c[i][j][0] + bi.x, c[i][j][1] + bi.y);
            float2 v1 = make_float2(c[i][j][2] + bi.x, c[i][j][3] + bi.y);
            size_t base = ((size_t)(b_ * HH + h) * SS + s_) * DH + dh;
            *(float2*)&O[base] = v0;
            *(float2*)&O[base + 8 * DH] = v1;
        }
    }
}

// ---------------------------------------------------------------------------
// K2: fused attention. Per CTA: (bh, 128 q-rows).
// Pass A: recomputable QK^T logits -> row sums of exp (registers only).
// Pass B: recompute logits, p = exp(s)*inv, write score ONCE, PV MMA (ctx^T).
// Dynamic smem layout (uint32 words):
//   Qs[128*68] @0     Ks[128*68] @8704   Vs[128*72] @17408
//   Ps[128*132] @26624 (reused as ctx staging)  invs[128] @43520  rowp[512] @43648
// ---------------------------------------------------------------------------
#define QS_O   0
#define KS_O   8704
#define VS_O   17408
#define PS_O   26624
#define INV_O  43520
#define RP_O   43648
#define SMEM_WORDS 44160
#define SMEM_BYTES (SMEM_WORDS * 4)

__global__ __launch_bounds__(256, 1) void k_attn(
    const float* __restrict__ mask, float* __restrict__ score)
{
    extern __shared__ uint32_t sm[];
    uint32_t* Qs = sm + QS_O;
    uint32_t* Ks = sm + KS_O;
    uint32_t* Vs = sm + VS_O;
    uint32_t* Ps = sm + PS_O;
    float* invs  = (float*)(sm + INV_O);
    float* rowp  = (float*)(sm + RP_O);

    int bh = blockIdx.y, q0 = blockIdx.x * 128;
    const float* Q = g_qh + (size_t)bh * SS * DH;
    const float* K = g_kh + (size_t)bh * SS * DH;
    const float* V = g_vh + (size_t)bh * SS * DH;

    int tid = threadIdx.x, lane = tid & 31, wid = tid >> 5;
    int g = lane >> 2, ct = lane & 3;
    int mb = (wid >> 2) * 64, nb = (wid & 3) * 32;   // QK warp tile 64x32
    int pm = (wid & 1) * 32, pn = (wid >> 1) * 32;   // PV warp tile (dh32 x q32)

    // Q tile (resident for entire kernel)
    #pragma unroll
    for (int it = 0; it < 8; it++) {
        int idx = tid + it * 256;
        int r = idx >> 4, c4 = (idx & 15) << 2;
        float4 a = *(const float4*)(Q + (size_t)(q0 + r) * DH + c4);
        *(uint4*)&Qs[r * 68 + c4] = make_uint4(tf32c(a.x), tf32c(a.y), tf32c(a.z), tf32c(a.w));
    }

    float cfr[4][4][4];
    float rs[4][2];
    #pragma unroll
    for (int i = 0; i < 4; i++) { rs[i][0] = 0.0f; rs[i][1] = 0.0f; }

    // ------------------ Pass A: row sums ------------------
    for (int n0 = 0; n0 < SS; n0 += 128) {
        __syncthreads();   // prev iter's Ks readers done (iter0: Qs stores done)
        #pragma unroll
        for (int it = 0; it < 8; it++) {
            int idx = tid + it * 256;
            int r = idx >> 4, c4 = (idx & 15) << 2;
            float4 a = *(const float4*)(K + (size_t)(n0 + r) * DH + c4);
            *(uint4*)&Ks[r * 68 + c4] = make_uint4(tf32c(a.x), tf32c(a.y), tf32c(a.z), tf32c(a.w));
        }
        __syncthreads();
        #pragma unroll
        for (int i = 0; i < 4; i++)
            #pragma unroll
            for (int j = 0; j < 4; j++)
                #pragma unroll
                for (int t = 0; t < 4; t++) cfr[i][j][t] = 0.0f;
        #pragma unroll
        for (int ks = 0; ks < DH; ks += 8) {
            uint32_t af[4][4], bf[4][2];
            #pragma unroll
            for (int i = 0; i < 4; i++) {
                int r0 = (mb + i * 16 + g) * 68 + ks + ct;
                af[i][0] = Qs[r0];       af[i][2] = Qs[r0 + 4];
                af[i][1] = Qs[r0 + 544]; af[i][3] = Qs[r0 + 548];
            }
            #pragma unroll
            for (int j = 0; j < 4; j++) {
                int b0 = (nb + j * 8 + g) * 68 + ks + ct;
                bf[j][0] = Ks[b0]; bf[j][1] = Ks[b0 + 4];
            }
            #pragma unroll
            for (int i = 0; i < 4; i++)
                #pragma unroll
                for (int j = 0; j < 4; j++) mma8(cfr[i][j], af[i], bf[j]);
        }
        // epilogue: accumulate sum(exp(s + mask)) in registers
        #pragma unroll
        for (int i = 0; i < 4; i++) {
            int row = q0 + mb + i * 16 + g;
            #pragma unroll
            for (int j = 0; j < 4; j++) {
                int col = n0 + nb + j * 8 + ct * 2;
                float2 mk0 = *(const float2*)&mask[(size_t)row * SS + col];
                float s0 = fmaf(cfr[i][j][0], 0.125f, mk0.x);
                float s1 = fmaf(cfr[i][j][1], 0.125f, mk0.y);
                rs[i][0] += fexp(s0) + fexp(s1);
                float2 mk1 = *(const float2*)&mask[(size_t)(row + 8) * SS + col];
                float s2 = fmaf(cfr[i][j][2], 0.125f, mk1.x);
                float s3 = fmaf(cfr[i][j][3], 0.125f, mk1.y);
                rs[i][1] += fexp(s2) + fexp(s3);
            }
        }
    }
    // reduce row sums: over quad (ct) lanes, then across the 4 n-strip warps
    #pragma unroll
    for (int i = 0; i < 4; i++) {
        #pragma unroll
        for (int h = 0; h < 2; h++) {
            float v = rs[i][h];
            v += __shfl_xor_sync(0xffffffff, v, 1);
            v += __shfl_xor_sync(0xffffffff, v, 2);
            if (ct == 0) rowp[(mb + i * 16 + h * 8 + g) * 4 + (wid & 3)] = v;
        }
    }
    __syncthreads();
    if (tid < 128)
        invs[tid] = 1.0f / (rowp[tid*4] + rowp[tid*4+1] + rowp[tid*4+2] + rowp[tid*4+3]);

    // ------------------ Pass B: score + ctx ------------------
    float d[2][4][4];
    #pragma unroll
    for (int i = 0; i < 2; i++)
        #pragma unroll
        for (int j = 0; j < 4; j++)
            #pragma unroll
            for (int t = 0; t < 4; t++) d[i][j][t] = 0.0f;

    size_t sbase = (size_t)bh * SS * SS;

    for (int n0 = 0; n0 < SS; n0 += 128) {
        __syncthreads();   // prev PV readers of Vs/Ps done; Ks readers done; invs visible
        #pragma unroll
        for (int it = 0; it < 8; it++) {
            int idx = tid + it * 256;
            int r = idx >> 4, c4 = (idx & 15) << 2;
            float4 a = *(const float4*)(K + (size_t)(n0 + r) * DH + c4);
            *(uint4*)&Ks[r * 68 + c4] = make_uint4(tf32c(a.x), tf32c(a.y), tf32c(a.z), tf32c(a.w));
            float4 vv = *(const float4*)(V + (size_t)(n0 + r) * DH + c4);
            *(uint4*)&Vs[r * 72 + c4] = make_uint4(tf32c(vv.x), tf32c(vv.y), tf32c(vv.z), tf32c(vv.w));
        }
        __syncthreads();
        #pragma unroll
        for (int i = 0; i < 4; i++)
            #pragma unroll
            for (int j = 0; j < 4; j++)
                #pragma unroll
                for (int t = 0; t < 4; t++) cfr[i][j][t] = 0.0f;
        #pragma unroll
        for (int ks = 0; ks < DH; ks += 8) {
            uint32_t af[4][4], bf[4][2];
            #pragma unroll
            for (int i = 0; i < 4; i++) {
                int r0 = (mb + i * 16 + g) * 68 + ks + ct;
                af[i][0] = Qs[r0];       af[i][2] = Qs[r0 + 4];
                af[i][1] = Qs[r0 + 544]; af[i][3] = Qs[r0 + 548];
            }
            #pragma unroll
            for (int j = 0; j < 4; j++) {
                int b0 = (nb + j * 8 + g) * 68 + ks + ct;
                bf[j][0] = Ks[b0]; bf[j][1] = Ks[b0 + 4];
            }
            #pragma unroll
            for (int i = 0; i < 4; i++)
                #pragma unroll
                for (int j = 0; j < 4; j++) mma8(cfr[i][j], af[i], bf[j]);
        }
        // epilogue: p = exp(s)*inv -> score gmem (once) + Ps smem (tf32)
        #pragma unroll
        for (int i = 0; i < 4; i++) {
            int row = mb + i * 16 + g;
            float iv0 = invs[row], iv1 = invs[row + 8];
            int grow = q0 + row;
            #pragma unroll
            for (int j = 0; j < 4; j++) {
                int col = nb + j * 8 + ct * 2;
                int gcol = n0 + col;
                float2 mk0 = *(const float2*)&mask[(size_t)grow * SS + gcol];
                float p0 = fexp(fmaf(cfr[i][j][0], 0.125f, mk0.x)) * iv0;
                float p1 = fexp(fmaf(cfr[i][j][1], 0.125f, mk0.y)) * iv0;
                *(float2*)&score[sbase + (size_t)grow * SS + gcol] = make_float2(p0, p1);
                Ps[row * 132 + col] = tf32c(p0);
                Ps[row * 132 + col + 1] = tf32c(p1);
                float2 mk1 = *(const float2*)&mask[(size_t)(grow + 8) * SS + gcol];
                float p2 = fexp(fmaf(cfr[i][j][2], 0.125f, mk1.x)) * iv1;
                float p3 = fexp(fmaf(cfr[i][j][3], 0.125f, mk1.y)) * iv1;
                *(float2*)&score[sbase + (size_t)(grow + 8) * SS + gcol] = make_float2(p2, p3);
                Ps[(row + 8) * 132 + col] = tf32c(p2);
                Ps[(row + 8) * 132 + col + 1] = tf32c(p3);
            }
        }
        __syncthreads();   // Ps visible to all
        // PV MMA: D = ctx^T = V^T (A, m=dh) x P^T (B, n=q), k = n-dim (128)
        #pragma unroll
        for (int ks = 0; ks < 128; ks += 8) {
            uint32_t af[2][4], bf[4][2];
            #pragma unroll
            for (int i = 0; i < 2; i++) {
                int a0 = (ks + ct) * 72 + pm + i * 16 + g;
                af[i][0] = Vs[a0];       af[i][1] = Vs[a0 + 8];
                af[i][2] = Vs[a0 + 288]; af[i][3] = Vs[a0 + 296];
            }
            #pragma unroll
            for (int j = 0; j < 4; j++) {
                int b0 = (pn + j * 8 + g) * 132 + ks + ct;
                bf[j][0] = Ps[b0]; bf[j][1] = Ps[b0 + 4];
            }
            #pragma unroll
            for (int i = 0; i < 2; i++)
                #pragma unroll
                for (int j = 0; j < 4; j++) mma8(d[i][j], af[i], bf[j]);
        }
    }
    __syncthreads();
    // stage ctx^T -> smem (reuse Ps as float [q=128][dh stride 68]) for coalesced STG
    float* ctxs = (float*)Ps;
    #pragma unroll
    for (int i = 0; i < 2; i++) {
        int dh = pm + i * 16 + g;
        #pragma unroll
        for (int j = 0; j < 4; j++) {
            int qq = pn + j * 8 + ct * 2;
            ctxs[qq * 68 + dh]           = d[i][j][0];
            ctxs[(qq + 1) * 68 + dh]     = d[i][j][1];
            ctxs[qq * 68 + dh + 8]       = d[i][j][2];
            ctxs[(qq + 1) * 68 + dh + 8] = d[i][j][3];
        }
    }
    __syncthreads();
    float* C = g_ctx + (size_t)bh * SS * DH + (size_t)q0 * DH;
    #pragma unroll
    for (int it = 0; it < 8; it++) {
        int idx = tid + it * 256;
        int r = idx >> 4, c4 = (idx & 15) << 2;
        *(float4*)(C + (size_t)r * DH + c4) = *(float4*)&ctxs[r * 68 + c4];
    }
}

// ---------------------------------------------------------------------------
// K4: output projection via tf32 mma. (unchanged from round 2)
// ---------------------------------------------------------------------------
__global__ __launch_bounds__(256) void k_oproj(
    const float* __restrict__ wo, const float* __restrict__ bo, float* __restrict__ out)
{
    __shared__ uint32_t As[128*20];
    __shared__ uint32_t Bs[128*20];
    int tid = threadIdx.x;
    int lane = tid & 31, wid = tid >> 5;
    int g = lane >> 2, ct = lane & 3;
    int mb = (wid >> 2) * 64, nb = (wid & 3) * 32;
    int m0 = blockIdx.y * 128, n0 = blockIdx.x * 128;

    float c[4][4][4];
    #pragma unroll
    for (int i = 0; i < 4; i++)
        #pragma unroll
        for (int j = 0; j < 4; j++)
            #pragma unroll
            for (int t = 0; t < 4; t++) c[i][j][t] = 0.0f;

    for (int k0 = 0; k0 < DM; k0 += 16) {
        #pragma unroll
        for (int u = 0; u < 2; u++) {
            int id = tid + u * 256;
            int r = id >> 2, c4 = (id & 3) << 2;
            int m = m0 + r;
            int b_ = m >> 11, s_ = m & (SS - 1);
            int kidx = k0 + c4;
            int h = kidx >> 6, dh = kidx & 63;
            float4 a = *(const float4*)(g_ctx + ((size_t)(b_ * HH + h) * SS + s_) * DH + dh);
            *(uint4*)&As[r * 20 + c4] = make_uint4(tf32c(a.x), tf32c(a.y), tf32c(a.z), tf32c(a.w));
            float4 w4 = *(const float4*)(wo + (size_t)(n0 + r) * DM + k0 + c4);
            *(uint4*)&Bs[r * 20 + c4] = make_uint4(tf32c(w4.x), tf32c(w4.y), tf32c(w4.z), tf32c(w4.w));
        }
        __syncthreads();
        #pragma unroll
        for (int ks = 0; ks < 16; ks += 8) {
            uint32_t af[4][4], bf[4][2];
            #pragma unroll
            for (int i = 0; i < 4; i++) {
                int r0 = (mb + i * 16 + g) * 20 + ks + ct;
                af[i][0] = As[r0];       af[i][2] = As[r0 + 4];
                af[i][1] = As[r0 + 160]; af[i][3] = As[r0 + 164];
            }
            #pragma unroll
            for (int j = 0; j < 4; j++) {
                int b0 = (nb + j * 8 + g) * 20 + ks + ct;
                bf[j][0] = Bs[b0]; bf[j][1] = Bs[b0 + 4];
            }
            #pragma unroll
            for (int i = 0; i < 4; i++)
                #pragma unroll
                for (int j = 0; j < 4; j++) mma8(c[i][j], af[i], bf[j]);
        }
        __syncthreads();
    }
    #pragma unroll
    for (int i = 0; i < 4; i++) {
        int row = m0 + mb + i * 16 + g;
        #pragma unroll
        for (int j = 0; j < 4; j++) {
            int col = n0 + nb + j * 8 + ct * 2;
            float2 bi = *(const float2*)&bo[col];
            *(float2*)&out[(size_t)row * DM + col] =
                make_float2(c[i][j][0] + bi.x, c[i][j][1] + bi.y);
            *(float2*)&out[(size_t)(row + 8) * DM + col] =
                make_float2(c[i][j][2] + bi.x, c[i][j][3] + bi.y);
        }
    }
}

// ---------------------------------------------------------------------------
extern "C" void kernel_launch(void* const* d_in, const int* in_sizes, int n_in,
                              void* d_out, int out_size)
{
    const float* q    = (const float*)d_in[0];
    const float* k    = (const float*)d_in[1];
    const float* v    = (const float*)d_in[2];
    const float* mask = (const float*)d_in[3];
    const float* w_q  = (const float*)d_in[4];
    const float* b_q  = (const float*)d_in[5];
    const float* w_k  = (const float*)d_in[6];
    const float* b_k  = (const float*)d_in[7];
    const float* w_v  = (const float*)d_in[8];
    const float* b_v  = (const float*)d_in[9];
    const float* w_o  = (const float*)d_in[10];
    const float* b_o  = (const float*)d_in[11];

    float* out   = (float*)d_out;                        // x: [B,S,DM]
    float* score = out + (size_t)BB * SS * DM;           // score: [B,H,S,S]

    cudaFuncSetAttribute(k_attn, cudaFuncAttributeMaxDynamicSharedMemorySize, SMEM_BYTES);

    k_qkv_proj<<<dim3(DM/128, (BB*SS)/128, 3), 256>>>(q, k, v, w_q, w_k, w_v, b_q, b_k, b_v);
    k_attn<<<dim3(SS/128, BHT), 256, SMEM_BYTES>>>(mask, score);
    k_oproj<<<dim3(DM/128, (BB*SS)/128), 256>>>(w_o, b_o, out);
}